// round 5
// baseline (speedup 1.0000x reference)
#include <cuda_runtime.h>

// GraphSAGE 2-layer: N=100000 nodes, E=6400000 edges, 14 -> 16 -> 8
//
// edge_index arrives as int32 [2, E] (JAX x64-disabled downcasts the int64 request).
//
// Pipeline (5 kernels, all graph-capturable, scratch in __device__ globals):
//   k_prep : pad x to 16 floats (slot14 = 1.0 for degree count), zero accumulators
//   k_edge1: per edge, gather xp[src] (4x float4, L2-resident) -> red.v4 into acc1[dst]
//   k_node1: mean = acc1/cnt ; h = relu(mean@W1l^T + b1 + x@W1r^T) ; g = h@W2l^T
//   k_edge2: per edge, gather g[src] (2x float4) -> red.v4 into acc2[dst]
//   k_node2: out = acc2/cnt + b2 + h@W2r^T

#define NN 100000
#define NE 6400000

__device__ __align__(16) float g_xp  [NN * 16];  // padded x, slot14 = 1.0
__device__ __align__(16) float g_acc1[NN * 16];  // sum xp over in-edges; slot14 = degree
__device__ __align__(16) float g_h   [NN * 16];  // layer-1 activations
__device__ __align__(16) float g_g   [NN * 8];   // h @ W2_l^T (pre-transformed for aggr)
__device__ __align__(16) float g_acc2[NN * 8];   // sum g over in-edges

__device__ __forceinline__ void red_add_v4(float* p, float a, float b, float c, float d) {
    asm volatile("red.global.add.v4.f32 [%0], {%1, %2, %3, %4};"
                 :: "l"(p), "f"(a), "f"(b), "f"(c), "f"(d) : "memory");
}

__global__ __launch_bounds__(256, 1) void k_prep(const float* __restrict__ x, int n) {
    int i = blockIdx.x * blockDim.x + threadIdx.x;
    if (i >= n) return;
    float r[16];
#pragma unroll
    for (int k = 0; k < 14; k++) r[k] = x[i * 14 + k];
    r[14] = 1.0f; r[15] = 0.0f;
    float4* o = (float4*)(g_xp + (size_t)i * 16);
#pragma unroll
    for (int q = 0; q < 4; q++)
        o[q] = make_float4(r[4*q], r[4*q+1], r[4*q+2], r[4*q+3]);
    float4 z = make_float4(0.f, 0.f, 0.f, 0.f);
    float4* a1 = (float4*)(g_acc1 + (size_t)i * 16);
    a1[0] = z; a1[1] = z; a1[2] = z; a1[3] = z;
    float4* a2 = (float4*)(g_acc2 + (size_t)i * 8);
    a2[0] = z; a2[1] = z;
}

__global__ __launch_bounds__(256, 1) void k_edge1(const int* __restrict__ ei, int ne) {
    for (int e = blockIdx.x * blockDim.x + threadIdx.x; e < ne;
         e += gridDim.x * blockDim.x) {
        int src = ei[e];
        int dst = ei[ne + e];
        const float4* xs = (const float4*)(g_xp + (size_t)src * 16);
        float4 a = xs[0], b = xs[1], c = xs[2], d = xs[3];
        float* p = g_acc1 + (size_t)dst * 16;
        red_add_v4(p +  0, a.x, a.y, a.z, a.w);
        red_add_v4(p +  4, b.x, b.y, b.z, b.w);
        red_add_v4(p +  8, c.x, c.y, c.z, c.w);
        red_add_v4(p + 12, d.x, d.y, d.z, d.w);
    }
}

__global__ __launch_bounds__(256, 1) void k_node1(
        const float* __restrict__ W1l, const float* __restrict__ b1,
        const float* __restrict__ W1r, const float* __restrict__ W2l, int n) {
    __shared__ float sW1l[16 * 14], sW1r[16 * 14], sb1[16], sW2l[8 * 16];
    int t = threadIdx.x;
    for (int k = t; k < 224; k += blockDim.x) sW1l[k] = W1l[k];
    for (int k = t; k < 224; k += blockDim.x) sW1r[k] = W1r[k];
    for (int k = t; k < 16;  k += blockDim.x) sb1[k]  = b1[k];
    for (int k = t; k < 128; k += blockDim.x) sW2l[k] = W2l[k];
    __syncthreads();
    int i = blockIdx.x * blockDim.x + t;
    if (i >= n) return;

    const float4* ap = (const float4*)(g_acc1 + (size_t)i * 16);
    float4 a0 = ap[0], a1 = ap[1], a2 = ap[2], a3 = ap[3];
    float acc[16] = {a0.x,a0.y,a0.z,a0.w, a1.x,a1.y,a1.z,a1.w,
                     a2.x,a2.y,a2.z,a2.w, a3.x,a3.y,a3.z,a3.w};
    float inv = 1.0f / fmaxf(acc[14], 1.0f);

    const float4* xp = (const float4*)(g_xp + (size_t)i * 16);
    float4 x0 = xp[0], x1 = xp[1], x2 = xp[2], x3 = xp[3];
    float xr[16] = {x0.x,x0.y,x0.z,x0.w, x1.x,x1.y,x1.z,x1.w,
                    x2.x,x2.y,x2.z,x2.w, x3.x,x3.y,x3.z,x3.w};

    float mk[14];
#pragma unroll
    for (int k = 0; k < 14; k++) mk[k] = acc[k] * inv;

    float h[16];
#pragma unroll
    for (int j = 0; j < 16; j++) {
        float s = sb1[j];
#pragma unroll
        for (int k = 0; k < 14; k++)
            s = fmaf(mk[k], sW1l[j * 14 + k], fmaf(xr[k], sW1r[j * 14 + k], s));
        h[j] = fmaxf(s, 0.0f);
    }
    float4* ho = (float4*)(g_h + (size_t)i * 16);
#pragma unroll
    for (int q = 0; q < 4; q++)
        ho[q] = make_float4(h[4*q], h[4*q+1], h[4*q+2], h[4*q+3]);

    float gg[8];
#pragma unroll
    for (int j = 0; j < 8; j++) {
        float s = 0.0f;
#pragma unroll
        for (int k = 0; k < 16; k++)
            s = fmaf(h[k], sW2l[j * 16 + k], s);
        gg[j] = s;
    }
    float4* go = (float4*)(g_g + (size_t)i * 8);
    go[0] = make_float4(gg[0], gg[1], gg[2], gg[3]);
    go[1] = make_float4(gg[4], gg[5], gg[6], gg[7]);
}

__global__ __launch_bounds__(256, 1) void k_edge2(const int* __restrict__ ei, int ne) {
    for (int e = blockIdx.x * blockDim.x + threadIdx.x; e < ne;
         e += gridDim.x * blockDim.x) {
        int src = ei[e];
        int dst = ei[ne + e];
        const float4* gs = (const float4*)(g_g + (size_t)src * 8);
        float4 a = gs[0], b = gs[1];
        float* p = g_acc2 + (size_t)dst * 8;
        red_add_v4(p + 0, a.x, a.y, a.z, a.w);
        red_add_v4(p + 4, b.x, b.y, b.z, b.w);
    }
}

__global__ __launch_bounds__(256, 1) void k_node2(
        const float* __restrict__ W2r, const float* __restrict__ b2,
        float* __restrict__ out, int n) {
    __shared__ float sW2r[8 * 16], sb2[8];
    int t = threadIdx.x;
    for (int k = t; k < 128; k += blockDim.x) sW2r[k] = W2r[k];
    for (int k = t; k < 8;   k += blockDim.x) sb2[k]  = b2[k];
    __syncthreads();
    int i = blockIdx.x * blockDim.x + t;
    if (i >= n) return;

    float inv = 1.0f / fmaxf(g_acc1[(size_t)i * 16 + 14], 1.0f);

    const float4* hp = (const float4*)(g_h + (size_t)i * 16);
    float4 h0 = hp[0], h1 = hp[1], h2 = hp[2], h3 = hp[3];
    float h[16] = {h0.x,h0.y,h0.z,h0.w, h1.x,h1.y,h1.z,h1.w,
                   h2.x,h2.y,h2.z,h2.w, h3.x,h3.y,h3.z,h3.w};

    const float4* ap = (const float4*)(g_acc2 + (size_t)i * 8);
    float4 s0 = ap[0], s1 = ap[1];
    float sm[8] = {s0.x,s0.y,s0.z,s0.w, s1.x,s1.y,s1.z,s1.w};

    float o[8];
#pragma unroll
    for (int j = 0; j < 8; j++) {
        float s = fmaf(sm[j], inv, sb2[j]);
#pragma unroll
        for (int k = 0; k < 16; k++)
            s = fmaf(h[k], sW2r[j * 16 + k], s);
        o[j] = s;
    }
    float4* op = (float4*)(out + (size_t)i * 8);
    op[0] = make_float4(o[0], o[1], o[2], o[3]);
    op[1] = make_float4(o[4], o[5], o[6], o[7]);
}

extern "C" void kernel_launch(void* const* d_in, const int* in_sizes, int n_in,
                              void* d_out, int out_size) {
    const float* x   = (const float*)d_in[0];
    const int*   ei  = (const int*)d_in[1];   // int32 [2, E] (JAX x64 disabled)
    // d_in[2] = edge_attr (unused by the reference)
    const float* W1l = (const float*)d_in[3];
    const float* b1  = (const float*)d_in[4];
    const float* W1r = (const float*)d_in[5];
    const float* W2l = (const float*)d_in[6];
    const float* b2  = (const float*)d_in[7];
    const float* W2r = (const float*)d_in[8];
    float* out = (float*)d_out;

    int n  = in_sizes[0] / 14;  // 100000
    int ne = in_sizes[1] / 2;   // 6400000

    const int TPB = 256;
    k_prep <<<(n  + TPB - 1) / TPB, TPB>>>(x, n);
    k_edge1<<<(ne + TPB - 1) / TPB, TPB>>>(ei, ne);
    k_node1<<<(n  + TPB - 1) / TPB, TPB>>>(W1l, b1, W1r, W2l, n);
    k_edge2<<<(ne + TPB - 1) / TPB, TPB>>>(ei, ne);
    k_node2<<<(n  + TPB - 1) / TPB, TPB>>>(W2r, b2, out, n);
}